// round 5
// baseline (speedup 1.0000x reference)
#include <cuda_runtime.h>
#include <math.h>

#define Bq 128
#define Sq 1024
#define Dq 512
#define Hq 512

#define BM 64
#define BN 128
#define BK 16
#define TM 4
#define TN 8

// Scratch (no allocations allowed -> __device__ globals)
__device__ float g_inp [Bq * Hq];   // input @ W_in.T + b_in
__device__ float g_att [Bq * Sq];   // raw (unmasked) scores
__device__ float g_cbar[Bq * Dq];   // alpha-weighted context

// ---------------------------------------------------------------------------
// Generic small linear: out[b,h] = bias[h] + dot(X[b,:], W[h,:])   (K = Dq)
// grid(Bq), 256 threads. X row staged in smem; W rows read via float4.
// ---------------------------------------------------------------------------
__global__ void k_lin(const float* __restrict__ X, const float* __restrict__ W,
                      const float* __restrict__ bias, float* __restrict__ out) {
    __shared__ float xs[Dq];
    const int b = blockIdx.x;
    for (int d = threadIdx.x; d < Dq; d += blockDim.x) xs[d] = X[b * Dq + d];
    __syncthreads();
    for (int h = threadIdx.x; h < Hq; h += blockDim.x) {
        const float4* w = (const float4*)(W + (size_t)h * Dq);
        float acc = 0.f;
#pragma unroll 8
        for (int i = 0; i < Dq / 4; i++) {
            float4 wv = w[i];
            acc += wv.x * xs[4 * i + 0] + wv.y * xs[4 * i + 1]
                 + wv.z * xs[4 * i + 2] + wv.w * xs[4 * i + 3];
        }
        out[b * Hq + h] = acc + bias[h];
    }
}

// ---------------------------------------------------------------------------
// Fused score GEMM:
//   for each (b, s-tile of 64): loop h-chunks of 128:
//     C[s,h] = context[b,s,:] . W_ctx[h,:]          (K = 512, double-buffered)
//     att[b,s] += sum_h V[h] * tanh(inp[b,h] + b_ctx[h] + C[s,h])
// ctx tensor (256 MB) never hits memory.
// ---------------------------------------------------------------------------
__global__ void __launch_bounds__(256, 2)
k_score(const float* __restrict__ context, const float* __restrict__ W_ctx,
        const float* __restrict__ b_ctx, const float* __restrict__ V) {
    __shared__ float As[2][BM * BK];      // [s][k]
    __shared__ float Bs[2][BK * BN];      // [k][h]
    __shared__ float att_sm[BM];
    __shared__ float pre_s[BN];           // inp + b_ctx for current h-chunk
    __shared__ float V_s[BN];

    const int b   = blockIdx.y;
    const int s0  = blockIdx.x * BM;
    const int tid = threadIdx.x;
    const int tx  = tid & 15;             // h dim (16)
    const int ty  = tid >> 4;             // s dim (16)

    if (tid < BM) att_sm[tid] = 0.f;

    const float* Abase = context + ((size_t)b * Sq + s0) * Dq;

    const int aRow = tid >> 2;            // 0..63  (s within tile)
    const int aCol = (tid & 3) * 4;       // k offset (float4)
    const int bRow = tid >> 2;            // 0..63  (h rows bRow, bRow+64)
    const int bCol = (tid & 3) * 4;       // k offset (float4)

    const int NT = Dq / BK;               // 32 k-tiles

    for (int hc = 0; hc < Hq; hc += BN) {
        __syncthreads();                  // protect pre_s/V_s vs prev epilogue

        if (tid < BN) {
            pre_s[tid] = g_inp[b * Hq + hc + tid] + b_ctx[hc + tid];
            V_s[tid]   = V[hc + tid];
        }

        float acc[TM][TN];
#pragma unroll
        for (int i = 0; i < TM; i++)
#pragma unroll
            for (int j = 0; j < TN; j++) acc[i][j] = 0.f;

        // preload k-tile 0 into buffer 0
        float4 pa  = *(const float4*)(Abase + (size_t)aRow * Dq + aCol);
        float4 pb0 = *(const float4*)(W_ctx + (size_t)(hc + bRow) * Dq + bCol);
        float4 pb1 = *(const float4*)(W_ctx + (size_t)(hc + bRow + 64) * Dq + bCol);
        *(float4*)&As[0][aRow * BK + aCol] = pa;
        {
            float pb0a[4] = {pb0.x, pb0.y, pb0.z, pb0.w};
            float pb1a[4] = {pb1.x, pb1.y, pb1.z, pb1.w};
#pragma unroll
            for (int j = 0; j < 4; j++) {
                Bs[0][(bCol + j) * BN + bRow]      = pb0a[j];
                Bs[0][(bCol + j) * BN + 64 + bRow] = pb1a[j];
            }
        }
        __syncthreads();

        for (int kt = 0; kt < NT; kt++) {
            const int cur = kt & 1;
            if (kt + 1 < NT) {
                const int k0 = (kt + 1) * BK;
                pa  = *(const float4*)(Abase + (size_t)aRow * Dq + k0 + aCol);
                pb0 = *(const float4*)(W_ctx + (size_t)(hc + bRow) * Dq + k0 + bCol);
                pb1 = *(const float4*)(W_ctx + (size_t)(hc + bRow + 64) * Dq + k0 + bCol);
            }
#pragma unroll
            for (int k = 0; k < BK; k++) {
                float a0 = As[cur][(ty * TM + 0) * BK + k];
                float a1 = As[cur][(ty * TM + 1) * BK + k];
                float a2 = As[cur][(ty * TM + 2) * BK + k];
                float a3 = As[cur][(ty * TM + 3) * BK + k];
                float4 bv0 = *(const float4*)&Bs[cur][k * BN + tx * TN];
                float4 bv1 = *(const float4*)&Bs[cur][k * BN + tx * TN + 4];
                float bb[TN] = {bv0.x, bv0.y, bv0.z, bv0.w,
                                bv1.x, bv1.y, bv1.z, bv1.w};
#pragma unroll
                for (int j = 0; j < TN; j++) {
                    acc[0][j] += a0 * bb[j];
                    acc[1][j] += a1 * bb[j];
                    acc[2][j] += a2 * bb[j];
                    acc[3][j] += a3 * bb[j];
                }
            }
            if (kt + 1 < NT) {
                const int nxt = cur ^ 1;
                *(float4*)&As[nxt][aRow * BK + aCol] = pa;
                float pb0a[4] = {pb0.x, pb0.y, pb0.z, pb0.w};
                float pb1a[4] = {pb1.x, pb1.y, pb1.z, pb1.w};
#pragma unroll
                for (int j = 0; j < 4; j++) {
                    Bs[nxt][(bCol + j) * BN + bRow]      = pb0a[j];
                    Bs[nxt][(bCol + j) * BN + 64 + bRow] = pb1a[j];
                }
            }
            __syncthreads();
        }

        // Epilogue: p[i] = sum over this thread's 8 h of V*tanh(pre + C)
        float p[TM] = {0.f, 0.f, 0.f, 0.f};
#pragma unroll
        for (int j = 0; j < TN; j++) {
            const float vj = V_s[tx * TN + j];
            const float pj = pre_s[tx * TN + j];
#pragma unroll
            for (int i = 0; i < TM; i++)
                p[i] += vj * tanhf(pj + acc[i][j]);
        }
        // reduce over tx (16 lanes of each half-warp)
#pragma unroll
        for (int i = 0; i < TM; i++) {
#pragma unroll
            for (int m = 1; m < 16; m <<= 1)
                p[i] += __shfl_xor_sync(0xffffffffu, p[i], m);
        }
        if (tx == 0) {                    // unique writer per s row
#pragma unroll
            for (int i = 0; i < TM; i++) att_sm[ty * TM + i] += p[i];
        }
    }
    __syncthreads();
    if (tid < BM) g_att[b * Sq + s0 + tid] = att_sm[tid];
}

// ---------------------------------------------------------------------------
// Masked softmax over S per row. grid(Bq), 256 threads x 4 elems.
// mask is int32 (bool inputs are materialized as int32 by the harness).
// ---------------------------------------------------------------------------
__global__ void k_softmax(const int* __restrict__ mask,
                          float* __restrict__ alpha) {
    const int b = blockIdx.x, tid = threadIdx.x;
    __shared__ float red[8];

    float v[4];
#pragma unroll
    for (int i = 0; i < 4; i++) {
        const int s = tid + i * 256;
        const float a = g_att[b * Sq + s];
        v[i] = mask[b * Sq + s] ? -INFINITY : a;
    }
    float m = fmaxf(fmaxf(v[0], v[1]), fmaxf(v[2], v[3]));
#pragma unroll
    for (int o = 16; o; o >>= 1) m = fmaxf(m, __shfl_xor_sync(~0u, m, o));
    if ((tid & 31) == 0) red[tid >> 5] = m;
    __syncthreads();
    m = red[0];
#pragma unroll
    for (int i = 1; i < 8; i++) m = fmaxf(m, red[i]);
    __syncthreads();

    float e[4], sum = 0.f;
#pragma unroll
    for (int i = 0; i < 4; i++) { e[i] = expf(v[i] - m); sum += e[i]; }
#pragma unroll
    for (int o = 16; o; o >>= 1) sum += __shfl_xor_sync(~0u, sum, o);
    if ((tid & 31) == 0) red[tid >> 5] = sum;
    __syncthreads();
    sum = 0.f;
#pragma unroll
    for (int i = 0; i < 8; i++) sum += red[i];
    const float inv = 1.f / sum;
#pragma unroll
    for (int i = 0; i < 4; i++)
        alpha[b * Sq + tid + i * 256] = e[i] * inv;
}

// ---------------------------------------------------------------------------
// c_bar[b,d] = sum_s alpha[b,s] * context[b,s,d].  grid(2, Bq), 256 threads.
// ---------------------------------------------------------------------------
__global__ void k_cbar(const float* __restrict__ context,
                       const float* __restrict__ alpha) {
    const int b = blockIdx.y;
    const int d = blockIdx.x * 256 + threadIdx.x;
    __shared__ float al[Sq];
    for (int s = threadIdx.x; s < Sq; s += 256) al[s] = alpha[b * Sq + s];
    __syncthreads();
    const float* cp = context + (size_t)b * Sq * Dq + d;
    float a0 = 0.f, a1 = 0.f, a2 = 0.f, a3 = 0.f;
    for (int s = 0; s < Sq; s += 4) {
        a0 += al[s + 0] * cp[(size_t)(s + 0) * Dq];
        a1 += al[s + 1] * cp[(size_t)(s + 1) * Dq];
        a2 += al[s + 2] * cp[(size_t)(s + 2) * Dq];
        a3 += al[s + 3] * cp[(size_t)(s + 3) * Dq];
    }
    g_cbar[b * Dq + d] = (a0 + a1) + (a2 + a3);
}

// ---------------------------------------------------------------------------
extern "C" void kernel_launch(void* const* d_in, const int* in_sizes, int n_in,
                              void* d_out, int out_size) {
    const float* input   = (const float*)d_in[0];
    const float* context = (const float*)d_in[1];
    const int*   mask    = (const int*)d_in[2];      // bool -> int32 in harness
    const float* W_in    = (const float*)d_in[3];
    const float* b_in    = (const float*)d_in[4];
    const float* W_ctx   = (const float*)d_in[5];
    const float* b_ctx   = (const float*)d_in[6];
    const float* V       = (const float*)d_in[7];

    float* hidden = (float*)d_out;                 // [B, H] first
    float* alpha  = (float*)d_out + Bq * Hq;       // [B, S] second

    float *p_inp = nullptr, *p_cbar = nullptr;
    cudaGetSymbolAddress((void**)&p_inp,  g_inp);
    cudaGetSymbolAddress((void**)&p_cbar, g_cbar);

    k_lin    <<<Bq, 256>>>(input, W_in, b_in, p_inp);
    k_score  <<<dim3(Sq / BM, Bq), 256>>>(context, W_ctx, b_ctx, V);
    k_softmax<<<Bq, 256>>>(mask, alpha);
    k_cbar   <<<dim3(2, Bq), 256>>>(context, alpha);
    k_lin    <<<Bq, 256>>>(p_cbar, W_ctx, b_ctx, hidden);
}

// round 7
// speedup vs baseline: 1.0060x; 1.0060x over previous
#include <cuda_runtime.h>
#include <math.h>

#define Bq 128
#define Sq 1024
#define Dq 512
#define Hq 512

#define BM 64
#define BN 128
#define BK 16
#define TM 4
#define TN 8

typedef unsigned long long u64;

// Scratch (no allocations allowed -> __device__ globals)
__device__ float g_inp [Bq * Hq];        // input @ W_in.T + b_in
__device__ float g_att [Bq * Sq];        // raw (unmasked) scores
__device__ float g_cbar[Bq * Dq];        // alpha-weighted context
__device__ float g_cbar_part[4][Bq * Dq];

// ---- packed fp32x2 helpers (Blackwell FFMA2; PTX-only pattern) -------------
__device__ __forceinline__ u64 pack_dup(float a) {
    u64 r; asm("mov.b64 %0, {%1, %1};" : "=l"(r) : "f"(a)); return r;
}
__device__ __forceinline__ void fma2(u64& d, u64 a, u64 b) {
    asm("fma.rn.f32x2 %0, %1, %2, %3;" : "=l"(d) : "l"(a), "l"(b), "l"(d));
}
__device__ __forceinline__ void unpack2(float& lo, float& hi, u64 v) {
    asm("mov.b64 {%0, %1}, %2;" : "=f"(lo), "=f"(hi) : "l"(v));
}

// ---------------------------------------------------------------------------
// Generic small linear: out[b,h] = bias[h] + dot(X[b,:], W[h,:])   (K = Dq)
// ---------------------------------------------------------------------------
__global__ void k_lin(const float* __restrict__ X, const float* __restrict__ W,
                      const float* __restrict__ bias, float* __restrict__ out) {
    __shared__ float xs[Dq];
    const int b = blockIdx.x;
    for (int d = threadIdx.x; d < Dq; d += blockDim.x) xs[d] = X[b * Dq + d];
    __syncthreads();
    for (int h = threadIdx.x; h < Hq; h += blockDim.x) {
        const float4* w = (const float4*)(W + (size_t)h * Dq);
        float acc = 0.f;
#pragma unroll 8
        for (int i = 0; i < Dq / 4; i++) {
            float4 wv = w[i];
            acc += wv.x * xs[4 * i + 0] + wv.y * xs[4 * i + 1]
                 + wv.z * xs[4 * i + 2] + wv.w * xs[4 * i + 3];
        }
        out[b * Hq + h] = acc + bias[h];
    }
}

// ---------------------------------------------------------------------------
// Fused score GEMM (FFMA2 mainloop):
//   C[s,h] = context[b,s,:] . W_ctx[h,:]   then
//   att[b,s] += sum_h V[h] * tanh(inp[b,h] + b_ctx[h] + C[s,h])
// ---------------------------------------------------------------------------
__global__ void __launch_bounds__(256, 2)
k_score(const float* __restrict__ context, const float* __restrict__ W_ctx,
        const float* __restrict__ b_ctx, const float* __restrict__ V) {
    __shared__ __align__(16) float As[2][BM * BK];   // [s][k]
    __shared__ __align__(16) float Bs[2][BK * BN];   // [k][h]
    __shared__ float att_sm[BM];
    __shared__ float pre_s[BN];
    __shared__ float V_s[BN];

    const int b   = blockIdx.y;
    const int s0  = blockIdx.x * BM;
    const int tid = threadIdx.x;
    const int tx  = tid & 15;             // h dim (16)
    const int ty  = tid >> 4;             // s dim (16)

    if (tid < BM) att_sm[tid] = 0.f;

    const float* Abase = context + ((size_t)b * Sq + s0) * Dq;

    const int aRow = tid >> 2;            // 0..63  (s within tile)
    const int aCol = (tid & 3) * 4;       // k offset (float4)
    const int bRow = tid >> 2;            // 0..63  (h rows bRow, bRow+64)
    const int bCol = (tid & 3) * 4;       // k offset (float4)

    const int NT = Dq / BK;               // 32 k-tiles

    for (int hc = 0; hc < Hq; hc += BN) {
        __syncthreads();                  // protect pre_s/V_s vs prev epilogue

        if (tid < BN) {
            pre_s[tid] = g_inp[b * Hq + hc + tid] + b_ctx[hc + tid];
            V_s[tid]   = V[hc + tid];
        }

        u64 acc2[TM][TN / 2];             // packed (h, h+1) accumulators
#pragma unroll
        for (int i = 0; i < TM; i++)
#pragma unroll
            for (int j = 0; j < TN / 2; j++) acc2[i][j] = 0ull;

        // preload k-tile 0 into buffer 0
        float4 pa  = *(const float4*)(Abase + (size_t)aRow * Dq + aCol);
        float4 pb0 = *(const float4*)(W_ctx + (size_t)(hc + bRow) * Dq + bCol);
        float4 pb1 = *(const float4*)(W_ctx + (size_t)(hc + bRow + 64) * Dq + bCol);
        *(float4*)&As[0][aRow * BK + aCol] = pa;
        {
            float pb0a[4] = {pb0.x, pb0.y, pb0.z, pb0.w};
            float pb1a[4] = {pb1.x, pb1.y, pb1.z, pb1.w};
#pragma unroll
            for (int j = 0; j < 4; j++) {
                Bs[0][(bCol + j) * BN + bRow]      = pb0a[j];
                Bs[0][(bCol + j) * BN + 64 + bRow] = pb1a[j];
            }
        }
        __syncthreads();

        for (int kt = 0; kt < NT; kt++) {
            const int cur = kt & 1;
            if (kt + 1 < NT) {
                const int k0 = (kt + 1) * BK;
                pa  = *(const float4*)(Abase + (size_t)aRow * Dq + k0 + aCol);
                pb0 = *(const float4*)(W_ctx + (size_t)(hc + bRow) * Dq + k0 + bCol);
                pb1 = *(const float4*)(W_ctx + (size_t)(hc + bRow + 64) * Dq + k0 + bCol);
            }
#pragma unroll
            for (int k = 0; k < BK; k++) {
                // b: 8 h-values = 4 packed pairs (two 128-bit shared loads)
                const ulonglong2* bp =
                    (const ulonglong2*)&Bs[cur][k * BN + tx * TN];
                ulonglong2 bq0 = bp[0];
                ulonglong2 bq1 = bp[1];
                u64 bb[4] = {bq0.x, bq0.y, bq1.x, bq1.y};
                // a: 4 s-values, duplicated into both lanes
                u64 ad[TM];
#pragma unroll
                for (int i = 0; i < TM; i++)
                    ad[i] = pack_dup(As[cur][(ty * TM + i) * BK + k]);
#pragma unroll
                for (int i = 0; i < TM; i++)
#pragma unroll
                    for (int j = 0; j < TN / 2; j++)
                        fma2(acc2[i][j], ad[i], bb[j]);
            }
            if (kt + 1 < NT) {
                const int nxt = cur ^ 1;
                *(float4*)&As[nxt][aRow * BK + aCol] = pa;
                float pb0a[4] = {pb0.x, pb0.y, pb0.z, pb0.w};
                float pb1a[4] = {pb1.x, pb1.y, pb1.z, pb1.w};
#pragma unroll
                for (int j = 0; j < 4; j++) {
                    Bs[nxt][(bCol + j) * BN + bRow]      = pb0a[j];
                    Bs[nxt][(bCol + j) * BN + 64 + bRow] = pb1a[j];
                }
            }
            __syncthreads();
        }

        // Epilogue: p[i] = sum over this thread's 8 h of V*tanh(pre + C)
        float p[TM] = {0.f, 0.f, 0.f, 0.f};
#pragma unroll
        for (int j = 0; j < TN / 2; j++) {
            const int h0 = tx * TN + 2 * j;
            const float v0 = V_s[h0],     pj0 = pre_s[h0];
            const float v1 = V_s[h0 + 1], pj1 = pre_s[h0 + 1];
#pragma unroll
            for (int i = 0; i < TM; i++) {
                float c0, c1;
                unpack2(c0, c1, acc2[i][j]);
                p[i] += v0 * tanhf(pj0 + c0) + v1 * tanhf(pj1 + c1);
            }
        }
#pragma unroll
        for (int i = 0; i < TM; i++) {
#pragma unroll
            for (int m = 1; m < 16; m <<= 1)
                p[i] += __shfl_xor_sync(0xffffffffu, p[i], m);
        }
        if (tx == 0) {                    // unique writer per s row
#pragma unroll
            for (int i = 0; i < TM; i++) att_sm[ty * TM + i] += p[i];
        }
    }
    __syncthreads();
    if (tid < BM) g_att[b * Sq + s0 + tid] = att_sm[tid];
}

// ---------------------------------------------------------------------------
// Masked softmax over S per row. grid(Bq), 256 threads x 4 elems.
// mask is int32 (bool inputs are materialized as int32 by the harness).
// ---------------------------------------------------------------------------
__global__ void k_softmax(const int* __restrict__ mask,
                          float* __restrict__ alpha) {
    const int b = blockIdx.x, tid = threadIdx.x;
    __shared__ float red[8];

    float v[4];
#pragma unroll
    for (int i = 0; i < 4; i++) {
        const int s = tid + i * 256;
        const float a = g_att[b * Sq + s];
        v[i] = mask[b * Sq + s] ? -INFINITY : a;
    }
    float m = fmaxf(fmaxf(v[0], v[1]), fmaxf(v[2], v[3]));
#pragma unroll
    for (int o = 16; o; o >>= 1) m = fmaxf(m, __shfl_xor_sync(~0u, m, o));
    if ((tid & 31) == 0) red[tid >> 5] = m;
    __syncthreads();
    m = red[0];
#pragma unroll
    for (int i = 1; i < 8; i++) m = fmaxf(m, red[i]);
    __syncthreads();

    float e[4], sum = 0.f;
#pragma unroll
    for (int i = 0; i < 4; i++) { e[i] = expf(v[i] - m); sum += e[i]; }
#pragma unroll
    for (int o = 16; o; o >>= 1) sum += __shfl_xor_sync(~0u, sum, o);
    if ((tid & 31) == 0) red[tid >> 5] = sum;
    __syncthreads();
    sum = 0.f;
#pragma unroll
    for (int i = 0; i < 8; i++) sum += red[i];
    const float inv = 1.f / sum;
#pragma unroll
    for (int i = 0; i < 4; i++)
        alpha[b * Sq + tid + i * 256] = e[i] * inv;
}

// ---------------------------------------------------------------------------
// Partial c_bar over an S-chunk of 256 rows (deterministic, no atomics).
// grid(2, 4, Bq), 256 threads. Then k_cbar_reduce sums the 4 partials.
// ---------------------------------------------------------------------------
__global__ void k_cbar(const float* __restrict__ context,
                       const float* __restrict__ alpha) {
    const int b  = blockIdx.z;
    const int sc = blockIdx.y;                       // s-chunk 0..3
    const int d  = blockIdx.x * 256 + threadIdx.x;
    const int s0 = sc * 256;
    __shared__ float al[256];
    al[threadIdx.x] = alpha[b * Sq + s0 + threadIdx.x];
    __syncthreads();
    const float* cp = context + ((size_t)b * Sq + s0) * Dq + d;
    float a0 = 0.f, a1 = 0.f, a2 = 0.f, a3 = 0.f;
    for (int s = 0; s < 256; s += 4) {
        a0 += al[s + 0] * cp[(size_t)(s + 0) * Dq];
        a1 += al[s + 1] * cp[(size_t)(s + 1) * Dq];
        a2 += al[s + 2] * cp[(size_t)(s + 2) * Dq];
        a3 += al[s + 3] * cp[(size_t)(s + 3) * Dq];
    }
    g_cbar_part[sc][b * Dq + d] = (a0 + a1) + (a2 + a3);
}

__global__ void k_cbar_reduce() {
    const int i = blockIdx.x * 256 + threadIdx.x;
    g_cbar[i] = (g_cbar_part[0][i] + g_cbar_part[1][i])
              + (g_cbar_part[2][i] + g_cbar_part[3][i]);
}

// ---------------------------------------------------------------------------
extern "C" void kernel_launch(void* const* d_in, const int* in_sizes, int n_in,
                              void* d_out, int out_size) {
    const float* input   = (const float*)d_in[0];
    const float* context = (const float*)d_in[1];
    const int*   mask    = (const int*)d_in[2];      // bool -> int32 in harness
    const float* W_in    = (const float*)d_in[3];
    const float* b_in    = (const float*)d_in[4];
    const float* W_ctx   = (const float*)d_in[5];
    const float* b_ctx   = (const float*)d_in[6];
    const float* V       = (const float*)d_in[7];

    float* hidden = (float*)d_out;                 // [B, H] first
    float* alpha  = (float*)d_out + Bq * Hq;       // [B, S] second

    float *p_inp = nullptr, *p_cbar = nullptr;
    cudaGetSymbolAddress((void**)&p_inp,  g_inp);
    cudaGetSymbolAddress((void**)&p_cbar, g_cbar);

    k_lin        <<<Bq, 256>>>(input, W_in, b_in, p_inp);
    k_score      <<<dim3(Sq / BM, Bq), 256>>>(context, W_ctx, b_ctx, V);
    k_softmax    <<<Bq, 256>>>(mask, alpha);
    k_cbar       <<<dim3(2, 4, Bq), 256>>>(context, alpha);
    k_cbar_reduce<<<Bq * Dq / 256, 256>>>();
    k_lin        <<<Bq, 256>>>(p_cbar, W_ctx, b_ctx, hidden);
}

// round 9
// speedup vs baseline: 2.6700x; 2.6540x over previous
#include <cuda_runtime.h>
#include <cuda_bf16.h>
#include <math.h>
#include <stdint.h>

#define Bq 128
#define Sq 1024
#define Dq 512
#define Hq 512

// ---------------- scratch (device globals; no allocs allowed) ---------------
__device__ float g_inp [Bq * Hq];
__device__ float g_att [Bq * Sq];
__device__ float g_cbar[Bq * Dq];
__device__ float g_cbar_part[4][Bq * Dq];
__device__ __nv_bfloat16 g_ctx_h[Bq * Sq * Dq];   // 128 MB
__device__ __nv_bfloat16 g_ctx_l[Bq * Sq * Dq];   // 128 MB
__device__ __nv_bfloat16 g_w_h  [Hq * Dq];
__device__ __nv_bfloat16 g_w_l  [Hq * Dq];

// ---------------- smem layout for k_mma (bytes) ------------------------------
// padded tiles: 128 rows x 48 B (16 bf16 data + 8 pad) -> conflict-free ldmatrix
#define RS      48
#define TILE_SZ (128 * RS)          // 6144
#define OF_AH   0                   // 2 bufs
#define OF_AL   12288
#define OF_BH   24576
#define OF_BL   36864
#define OF_PRE  49152               // 512 floats
#define OF_V    51200               // 512 floats
#define OF_ATTW 53248               // 4 x 128 floats
#define SMEM_SZ 55296

// ---------------- PTX helpers ------------------------------------------------
__device__ __forceinline__ uint32_t smem_u32(const void* p) {
    uint32_t a;
    asm("{ .reg .u64 t; cvta.to.shared.u64 t, %1; cvt.u32.u64 %0, t; }"
        : "=r"(a) : "l"(p));
    return a;
}
__device__ __forceinline__ void cp16(uint32_t dst, const void* src) {
    asm volatile("cp.async.cg.shared.global [%0], [%1], 16;"
                 :: "r"(dst), "l"(src) : "memory");
}
__device__ __forceinline__ void cp_commit() {
    asm volatile("cp.async.commit_group;" ::: "memory");
}
__device__ __forceinline__ void cp_wait1() {
    asm volatile("cp.async.wait_group 1;" ::: "memory");
}
__device__ __forceinline__ void cp_wait0() {
    asm volatile("cp.async.wait_group 0;" ::: "memory");
}
__device__ __forceinline__ void ldsm_x4(uint32_t& r0, uint32_t& r1,
                                        uint32_t& r2, uint32_t& r3,
                                        uint32_t addr) {
    asm volatile("ldmatrix.sync.aligned.m8n8.x4.shared.b16 {%0,%1,%2,%3}, [%4];"
                 : "=r"(r0), "=r"(r1), "=r"(r2), "=r"(r3) : "r"(addr));
}
__device__ __forceinline__ void mma16816(float* c, const uint32_t* a,
                                         const uint32_t* b) {
    asm volatile(
        "mma.sync.aligned.m16n8k16.row.col.f32.bf16.bf16.f32 "
        "{%0,%1,%2,%3}, {%4,%5,%6,%7}, {%8,%9}, {%0,%1,%2,%3};"
        : "+f"(c[0]), "+f"(c[1]), "+f"(c[2]), "+f"(c[3])
        : "r"(a[0]), "r"(a[1]), "r"(a[2]), "r"(a[3]), "r"(b[0]), "r"(b[1]));
}

// ---------------- fast tanh: FMA-only rational (Eigen/XLA), no MUFU ----------
__device__ __forceinline__ float fast_tanh(float x) {
    x = fminf(fmaxf(x, -7.99881172f), 7.99881172f);
    const float x2 = x * x;
    float p = fmaf(x2, -2.76076847742355e-16f, 2.00018790482477e-13f);
    p = fmaf(p, x2, -8.60467152213735e-11f);
    p = fmaf(p, x2,  5.12229709037114e-08f);
    p = fmaf(p, x2,  1.48572235717979e-05f);
    p = fmaf(p, x2,  6.37261928875436e-04f);
    p = fmaf(p, x2,  4.89352455891786e-03f);
    p *= x;
    float q = fmaf(x2, 1.19825839466702e-06f, 1.18534705686654e-04f);
    q = fmaf(q, x2, 2.26843463243900e-03f);
    q = fmaf(q, x2, 4.89352518554385e-03f);
    // reciprocal of q via bit-trick seed + 3 Newton steps (FMA pipe only)
    float r = __uint_as_float(0x7EF311C3u - __float_as_uint(q));
    r = r * (2.0f - q * r);
    r = r * (2.0f - q * r);
    r = r * (2.0f - q * r);
    return p * r;
}

// ---------------------------------------------------------------------------
// bf16 hi/lo split: x = hi + lo with hi = bf16(x)
// ---------------------------------------------------------------------------
__device__ __forceinline__ uint32_t pack_bf2(float a, float b) {
    __nv_bfloat162 t;
    t.x = __float2bfloat16(a);
    t.y = __float2bfloat16(b);
    return *(uint32_t*)&t;
}
__global__ void k_split(const float4* __restrict__ src,
                        uint2* __restrict__ dh, uint2* __restrict__ dl, int n4) {
    int i = blockIdx.x * 256 + threadIdx.x;
    if (i >= n4) return;
    float4 v = src[i];
    float h0 = __bfloat162float(__float2bfloat16(v.x));
    float h1 = __bfloat162float(__float2bfloat16(v.y));
    float h2 = __bfloat162float(__float2bfloat16(v.z));
    float h3 = __bfloat162float(__float2bfloat16(v.w));
    uint2 H, L;
    H.x = pack_bf2(h0, h1);            H.y = pack_bf2(h2, h3);
    L.x = pack_bf2(v.x - h0, v.y - h1);
    L.y = pack_bf2(v.z - h2, v.w - h3);
    dh[i] = H;  dl[i] = L;
}

// ---------------------------------------------------------------------------
// k_lin: out[b,h] = bias[h] + dot(X[b,:], W[h,:])
// ---------------------------------------------------------------------------
__global__ void k_lin(const float* __restrict__ X, const float* __restrict__ W,
                      const float* __restrict__ bias, float* __restrict__ out) {
    __shared__ float xs[Dq];
    const int b = blockIdx.x;
    for (int d = threadIdx.x; d < Dq; d += blockDim.x) xs[d] = X[b * Dq + d];
    __syncthreads();
    for (int h = threadIdx.x; h < Hq; h += blockDim.x) {
        const float4* w = (const float4*)(W + (size_t)h * Dq);
        float acc = 0.f;
#pragma unroll 8
        for (int i = 0; i < Dq / 4; i++) {
            float4 wv = w[i];
            acc += wv.x * xs[4 * i + 0] + wv.y * xs[4 * i + 1]
                 + wv.z * xs[4 * i + 2] + wv.w * xs[4 * i + 3];
        }
        out[b * Hq + h] = acc + bias[h];
    }
}

// ---------------------------------------------------------------------------
// Stage one BK=16 k-slab of A(hi,lo) and B(hi,lo) via cp.async.
// Each thread: 4 x 16B chunks (one per tile t: AH, AL, BH, BL).
// ---------------------------------------------------------------------------
__device__ __forceinline__ void stage(uint32_t sb, int buf, size_t aBase,
                                      int hc, int kt, int tid) {
    const int row  = tid >> 1;
    const int half = tid & 1;
    const int koff = kt * 16 + half * 8;
    const uint32_t d0 = sb + buf * TILE_SZ + row * RS + half * 16;
    cp16(d0 + OF_AH, g_ctx_h + aBase + (size_t)row * Dq + koff);
    cp16(d0 + OF_AL, g_ctx_l + aBase + (size_t)row * Dq + koff);
    cp16(d0 + OF_BH, g_w_h   + (size_t)(hc + row) * Dq + koff);
    cp16(d0 + OF_BL, g_w_l   + (size_t)(hc + row) * Dq + koff);
}

// ---------------------------------------------------------------------------
// HMMA fused score GEMM. grid(8, 128), 256 threads (8 warps, 2m x 4n).
// CTA: 128 s-rows x (4 h-chunks of 128); K=512 in 32 steps of 16, 2-stage.
// 3-product bf16 split: Ah*Bh + Ah*Bl + Al*Bh, fp32 accum.
// Epilogue: att[s] = sum_h V[h] * tanh(pre[h] + C[s,h]) (FMA-only tanh).
// ---------------------------------------------------------------------------
__global__ void __launch_bounds__(256)
k_mma(const float* __restrict__ b_ctx, const float* __restrict__ V) {
    extern __shared__ __align__(16) char smem[];
    const uint32_t sb = smem_u32(smem);
    const int tid  = threadIdx.x;
    const int wid  = tid >> 5;
    const int lane = tid & 31;
    const int wm   = wid & 1;        // m-warp: rows wm*64..+63
    const int wn   = wid >> 1;       // n-warp: cols wn*32..+31
    const int b    = blockIdx.y;
    const int s0   = blockIdx.x * 128;
    const size_t aBase = ((size_t)b * Sq + s0) * Dq;

    float* pre_s = (float*)(smem + OF_PRE);
    float* V_s   = (float*)(smem + OF_V);
    float* attw  = (float*)(smem + OF_ATTW);

    for (int i = tid; i < Hq; i += 256) {
        pre_s[i] = g_inp[b * Hq + i] + b_ctx[i];
        V_s[i]   = V[i];
    }
    __syncthreads();

    // ldmatrix per-lane byte offsets within a tile
    const uint32_t aoff = (uint32_t)((wm * 64 + (lane & 15)) * RS + (lane >> 4) * 16);
    const uint32_t boff = (uint32_t)((wn * 32 + (lane & 15)) * RS + (lane >> 4) * 16);

    float p[8];
#pragma unroll
    for (int i = 0; i < 8; i++) p[i] = 0.f;

    for (int hci = 0; hci < 4; hci++) {
        const int hc = hci * 128;

        float acc[4][4][4];
#pragma unroll
        for (int mi = 0; mi < 4; mi++)
#pragma unroll
            for (int nj = 0; nj < 4; nj++)
#pragma unroll
                for (int r = 0; r < 4; r++) acc[mi][nj][r] = 0.f;

        stage(sb, 0, aBase, hc, 0, tid);
        cp_commit();

        for (int kt = 0; kt < 32; kt++) {
            const int buf = kt & 1;
            if (kt < 31) {
                stage(sb, buf ^ 1, aBase, hc, kt + 1, tid);
                cp_commit();
                cp_wait1();
            } else {
                cp_wait0();
            }
            __syncthreads();

            const uint32_t bufo = sb + buf * TILE_SZ;
            uint32_t ah[4][4], al[4][4], bh[4][2], bl[4][2];
#pragma unroll
            for (int mi = 0; mi < 4; mi++) {
                ldsm_x4(ah[mi][0], ah[mi][1], ah[mi][2], ah[mi][3],
                        bufo + OF_AH + aoff + mi * (16 * RS));
                ldsm_x4(al[mi][0], al[mi][1], al[mi][2], al[mi][3],
                        bufo + OF_AL + aoff + mi * (16 * RS));
            }
#pragma unroll
            for (int ni = 0; ni < 2; ni++) {
                uint32_t r0, r1, r2, r3;
                ldsm_x4(r0, r1, r2, r3, bufo + OF_BH + boff + ni * (16 * RS));
                bh[ni * 2][0] = r0; bh[ni * 2][1] = r2;
                bh[ni * 2 + 1][0] = r1; bh[ni * 2 + 1][1] = r3;
                ldsm_x4(r0, r1, r2, r3, bufo + OF_BL + boff + ni * (16 * RS));
                bl[ni * 2][0] = r0; bl[ni * 2][1] = r2;
                bl[ni * 2 + 1][0] = r1; bl[ni * 2 + 1][1] = r3;
            }
#pragma unroll
            for (int mi = 0; mi < 4; mi++)
#pragma unroll
                for (int nj = 0; nj < 4; nj++) {
                    mma16816(acc[mi][nj], ah[mi], bh[nj]);
                    mma16816(acc[mi][nj], ah[mi], bl[nj]);
                    mma16816(acc[mi][nj], al[mi], bh[nj]);
                }
            __syncthreads();
        }

        // epilogue for this h-chunk: p += V*tanh(pre + C)
#pragma unroll
        for (int mi = 0; mi < 4; mi++)
#pragma unroll
            for (int nj = 0; nj < 4; nj++) {
                const int n0 = hc + wn * 32 + nj * 8 + (lane & 3) * 2;
                const float v0 = V_s[n0],     q0 = pre_s[n0];
                const float v1 = V_s[n0 + 1], q1 = pre_s[n0 + 1];
                p[mi * 2] += v0 * fast_tanh(q0 + acc[mi][nj][0])
                           + v1 * fast_tanh(q1 + acc[mi][nj][1]);
                p[mi * 2 + 1] += v0 * fast_tanh(q0 + acc[mi][nj][2])
                               + v1 * fast_tanh(q1 + acc[mi][nj][3]);
            }
    }

    // reduce over the 4 lanes sharing each row (lane quads), combine warps
#pragma unroll
    for (int i = 0; i < 8; i++) {
        p[i] += __shfl_xor_sync(0xffffffffu, p[i], 1);
        p[i] += __shfl_xor_sync(0xffffffffu, p[i], 2);
    }
    if ((lane & 3) == 0) {
#pragma unroll
        for (int mi = 0; mi < 4; mi++)
#pragma unroll
            for (int hf = 0; hf < 2; hf++) {
                const int row = wm * 64 + mi * 16 + (lane >> 2) + hf * 8;
                attw[wn * 128 + row] = p[mi * 2 + hf];
            }
    }
    __syncthreads();
    if (tid < 128)
        g_att[b * Sq + s0 + tid] = (attw[tid] + attw[128 + tid])
                                 + (attw[256 + tid] + attw[384 + tid]);
}

// ---------------------------------------------------------------------------
// Masked softmax over S per row (mask int32).
// ---------------------------------------------------------------------------
__global__ void k_softmax(const int* __restrict__ mask,
                          float* __restrict__ alpha) {
    const int b = blockIdx.x, tid = threadIdx.x;
    __shared__ float red[8];
    float v[4];
#pragma unroll
    for (int i = 0; i < 4; i++) {
        const int s = tid + i * 256;
        const float a = g_att[b * Sq + s];
        v[i] = mask[b * Sq + s] ? -INFINITY : a;
    }
    float m = fmaxf(fmaxf(v[0], v[1]), fmaxf(v[2], v[3]));
#pragma unroll
    for (int o = 16; o; o >>= 1) m = fmaxf(m, __shfl_xor_sync(~0u, m, o));
    if ((tid & 31) == 0) red[tid >> 5] = m;
    __syncthreads();
    m = red[0];
#pragma unroll
    for (int i = 1; i < 8; i++) m = fmaxf(m, red[i]);
    __syncthreads();
    float e[4], sum = 0.f;
#pragma unroll
    for (int i = 0; i < 4; i++) { e[i] = expf(v[i] - m); sum += e[i]; }
#pragma unroll
    for (int o = 16; o; o >>= 1) sum += __shfl_xor_sync(~0u, sum, o);
    if ((tid & 31) == 0) red[tid >> 5] = sum;
    __syncthreads();
    sum = 0.f;
#pragma unroll
    for (int i = 0; i < 8; i++) sum += red[i];
    const float inv = 1.f / sum;
#pragma unroll
    for (int i = 0; i < 4; i++)
        alpha[b * Sq + tid + i * 256] = e[i] * inv;
}

// ---------------------------------------------------------------------------
// c_bar partials + reduce (deterministic, no atomics).
// ---------------------------------------------------------------------------
__global__ void k_cbar(const float* __restrict__ context,
                       const float* __restrict__ alpha) {
    const int b  = blockIdx.z;
    const int sc = blockIdx.y;
    const int d  = blockIdx.x * 256 + threadIdx.x;
    const int s0 = sc * 256;
    __shared__ float al[256];
    al[threadIdx.x] = alpha[b * Sq + s0 + threadIdx.x];
    __syncthreads();
    const float* cp = context + ((size_t)b * Sq + s0) * Dq + d;
    float a0 = 0.f, a1 = 0.f, a2 = 0.f, a3 = 0.f;
    for (int s = 0; s < 256; s += 4) {
        a0 += al[s + 0] * cp[(size_t)(s + 0) * Dq];
        a1 += al[s + 1] * cp[(size_t)(s + 1) * Dq];
        a2 += al[s + 2] * cp[(size_t)(s + 2) * Dq];
        a3 += al[s + 3] * cp[(size_t)(s + 3) * Dq];
    }
    g_cbar_part[sc][b * Dq + d] = (a0 + a1) + (a2 + a3);
}
__global__ void k_cbar_reduce() {
    const int i = blockIdx.x * 256 + threadIdx.x;
    g_cbar[i] = (g_cbar_part[0][i] + g_cbar_part[1][i])
              + (g_cbar_part[2][i] + g_cbar_part[3][i]);
}

// ---------------------------------------------------------------------------
extern "C" void kernel_launch(void* const* d_in, const int* in_sizes, int n_in,
                              void* d_out, int out_size) {
    const float* input   = (const float*)d_in[0];
    const float* context = (const float*)d_in[1];
    const int*   mask    = (const int*)d_in[2];
    const float* W_in    = (const float*)d_in[3];
    const float* b_in    = (const float*)d_in[4];
    const float* W_ctx   = (const float*)d_in[5];
    const float* b_ctx   = (const float*)d_in[6];
    const float* V       = (const float*)d_in[7];

    float* hidden = (float*)d_out;
    float* alpha  = (float*)d_out + Bq * Hq;

    float *p_inp = nullptr, *p_cbar = nullptr;
    void  *p_ch = nullptr, *p_cl = nullptr, *p_wh = nullptr, *p_wl = nullptr;
    cudaGetSymbolAddress((void**)&p_inp,  g_inp);
    cudaGetSymbolAddress((void**)&p_cbar, g_cbar);
    cudaGetSymbolAddress(&p_ch, g_ctx_h);
    cudaGetSymbolAddress(&p_cl, g_ctx_l);
    cudaGetSymbolAddress(&p_wh, g_w_h);
    cudaGetSymbolAddress(&p_wl, g_w_l);

    cudaFuncSetAttribute(k_mma, cudaFuncAttributeMaxDynamicSharedMemorySize,
                         SMEM_SZ);

    const int n4c = Bq * Sq * Dq / 4;
    const int n4w = Hq * Dq / 4;
    k_split<<<n4c / 256, 256>>>((const float4*)context,
                                (uint2*)p_ch, (uint2*)p_cl, n4c);
    k_split<<<n4w / 256, 256>>>((const float4*)W_ctx,
                                (uint2*)p_wh, (uint2*)p_wl, n4w);
    k_lin  <<<Bq, 256>>>(input, W_in, b_in, p_inp);
    k_mma  <<<dim3(Sq / 128, Bq), 256, SMEM_SZ>>>(b_ctx, V);
    k_softmax<<<Bq, 256>>>(mask, alpha);
    k_cbar <<<dim3(2, 4, Bq), 256>>>(context, alpha);
    k_cbar_reduce<<<Bq * Dq / 256, 256>>>();
    k_lin  <<<Bq, 256>>>(p_cbar, W_ctx, b_ctx, hidden);
}

// round 10
// speedup vs baseline: 2.8284x; 1.0593x over previous
#include <cuda_runtime.h>
#include <cuda_bf16.h>
#include <math.h>
#include <stdint.h>

#define Bq 128
#define Sq 1024
#define Dq 512
#define Hq 512

// ---------------- scratch (device globals; no allocs allowed) ---------------
__device__ float g_inp [Bq * Hq];
__device__ float g_att [Bq * Sq];
__device__ float g_cbar[Bq * Dq];
__device__ float g_cbar_part[4][Bq * Dq];
__device__ __nv_bfloat16 g_ctx_h[Bq * Sq * Dq];   // 128 MB
__device__ __nv_bfloat16 g_ctx_l[Bq * Sq * Dq];   // 128 MB
__device__ __nv_bfloat16 g_w_h  [Hq * Dq];
__device__ __nv_bfloat16 g_w_l  [Hq * Dq];

// ---------------- smem layout for k_mma (bytes) ------------------------------
// BK=32 slabs: 128 rows x 80 B (64 B data + 16 B pad). Row stride 80 B = 20
// banks -> 8 consecutive rows hit distinct bank groups (conflict-free ldmatrix).
#define RS      80
#define TSZ     (128 * RS)          // 10240 per tile per buffer
#define OF_AH   0                   // [2][TSZ]
#define OF_AL   20480
#define OF_BH   40960
#define OF_BL   61440
#define OF_PRE  81920               // 512 floats
#define OF_V    83968               // 512 floats
#define OF_ATTW 86016               // 4 x 128 floats
#define SMEM_SZ 88064

// ---------------- PTX helpers ------------------------------------------------
__device__ __forceinline__ uint32_t smem_u32(const void* p) {
    uint32_t a;
    asm("{ .reg .u64 t; cvta.to.shared.u64 t, %1; cvt.u32.u64 %0, t; }"
        : "=r"(a) : "l"(p));
    return a;
}
__device__ __forceinline__ void cp16(uint32_t dst, const void* src) {
    asm volatile("cp.async.cg.shared.global [%0], [%1], 16;"
                 :: "r"(dst), "l"(src) : "memory");
}
__device__ __forceinline__ void cp_commit() {
    asm volatile("cp.async.commit_group;" ::: "memory");
}
__device__ __forceinline__ void cp_wait0() {
    asm volatile("cp.async.wait_group 0;" ::: "memory");
}
__device__ __forceinline__ void ldsm_x4(uint32_t& r0, uint32_t& r1,
                                        uint32_t& r2, uint32_t& r3,
                                        uint32_t addr) {
    asm volatile("ldmatrix.sync.aligned.m8n8.x4.shared.b16 {%0,%1,%2,%3}, [%4];"
                 : "=r"(r0), "=r"(r1), "=r"(r2), "=r"(r3) : "r"(addr));
}
__device__ __forceinline__ void mma16816(float* c, const uint32_t* a,
                                         const uint32_t* b) {
    asm volatile(
        "mma.sync.aligned.m16n8k16.row.col.f32.bf16.bf16.f32 "
        "{%0,%1,%2,%3}, {%4,%5,%6,%7}, {%8,%9}, {%0,%1,%2,%3};"
        : "+f"(c[0]), "+f"(c[1]), "+f"(c[2]), "+f"(c[3])
        : "r"(a[0]), "r"(a[1]), "r"(a[2]), "r"(a[3]), "r"(b[0]), "r"(b[1]));
}

// ---------------- fast tanh: FMA-only rational, no MUFU ----------------------
__device__ __forceinline__ float fast_tanh(float x) {
    x = fminf(fmaxf(x, -7.99881172f), 7.99881172f);
    const float x2 = x * x;
    float p = fmaf(x2, -2.76076847742355e-16f, 2.00018790482477e-13f);
    p = fmaf(p, x2, -8.60467152213735e-11f);
    p = fmaf(p, x2,  5.12229709037114e-08f);
    p = fmaf(p, x2,  1.48572235717979e-05f);
    p = fmaf(p, x2,  6.37261928875436e-04f);
    p = fmaf(p, x2,  4.89352455891786e-03f);
    p *= x;
    float q = fmaf(x2, 1.19825839466702e-06f, 1.18534705686654e-04f);
    q = fmaf(q, x2, 2.26843463243900e-03f);
    q = fmaf(q, x2, 4.89352518554385e-03f);
    float r = __uint_as_float(0x7EF311C3u - __float_as_uint(q));
    r = r * (2.0f - q * r);
    r = r * (2.0f - q * r);
    r = r * (2.0f - q * r);
    return p * r;
}

// ---------------------------------------------------------------------------
// bf16 hi/lo split
// ---------------------------------------------------------------------------
__device__ __forceinline__ uint32_t pack_bf2(float a, float b) {
    __nv_bfloat162 t;
    t.x = __float2bfloat16(a);
    t.y = __float2bfloat16(b);
    return *(uint32_t*)&t;
}
__global__ void k_split(const float4* __restrict__ src,
                        uint2* __restrict__ dh, uint2* __restrict__ dl, int n4) {
    int i = blockIdx.x * 256 + threadIdx.x;
    if (i >= n4) return;
    float4 v = src[i];
    float h0 = __bfloat162float(__float2bfloat16(v.x));
    float h1 = __bfloat162float(__float2bfloat16(v.y));
    float h2 = __bfloat162float(__float2bfloat16(v.z));
    float h3 = __bfloat162float(__float2bfloat16(v.w));
    uint2 H, L;
    H.x = pack_bf2(h0, h1);            H.y = pack_bf2(h2, h3);
    L.x = pack_bf2(v.x - h0, v.y - h1);
    L.y = pack_bf2(v.z - h2, v.w - h3);
    dh[i] = H;  dl[i] = L;
}

// ---------------------------------------------------------------------------
// k_lin
// ---------------------------------------------------------------------------
__global__ void k_lin(const float* __restrict__ X, const float* __restrict__ W,
                      const float* __restrict__ bias, float* __restrict__ out) {
    __shared__ float xs[Dq];
    const int b = blockIdx.x;
    for (int d = threadIdx.x; d < Dq; d += blockDim.x) xs[d] = X[b * Dq + d];
    __syncthreads();
    for (int h = threadIdx.x; h < Hq; h += blockDim.x) {
        const float4* w = (const float4*)(W + (size_t)h * Dq);
        float acc = 0.f;
#pragma unroll 8
        for (int i = 0; i < Dq / 4; i++) {
            float4 wv = w[i];
            acc += wv.x * xs[4 * i + 0] + wv.y * xs[4 * i + 1]
                 + wv.z * xs[4 * i + 2] + wv.w * xs[4 * i + 3];
        }
        out[b * Hq + h] = acc + bias[h];
    }
}

// ---------------------------------------------------------------------------
// HMMA fused score GEMM. grid(8, 128), 256 threads (8 warps, 2m x 4n).
// 64 pipeline steps = 4 h-chunks x 16 K-slabs of 32. One __syncthreads/step.
// Products ordered outermost (AhBh, AhBl, AlBh): 16 indep MMAs between
// accumulator reuses. Epilogue (tanh) overlaps next chunk's cp.async.
// ---------------------------------------------------------------------------
__global__ void __launch_bounds__(256)
k_mma(const float* __restrict__ b_ctx, const float* __restrict__ V) {
    extern __shared__ __align__(16) char smem[];
    const uint32_t sb = smem_u32(smem);
    const int tid  = threadIdx.x;
    const int wid  = tid >> 5;
    const int lane = tid & 31;
    const int wm   = wid & 1;        // rows wm*64..+63
    const int wn   = wid >> 1;       // cols wn*32..+31
    const int b    = blockIdx.y;
    const int s0   = blockIdx.x * 128;

    float* pre_s = (float*)(smem + OF_PRE);
    float* V_s   = (float*)(smem + OF_V);
    float* attw  = (float*)(smem + OF_ATTW);

    for (int i = tid; i < Hq; i += 256) {
        pre_s[i] = g_inp[b * Hq + i] + b_ctx[i];
        V_s[i]   = V[i];
    }

    // per-thread staging bases: row = tid>>1, two 16B segs (tid&1 selects pair)
    const int srow = tid >> 1;
    const int sseg = (tid & 1) * 2;
    const uint32_t sdst = sb + (uint32_t)(srow * RS + sseg * 16);
    const __nv_bfloat16* pAh = g_ctx_h + ((size_t)(b * Sq) + s0 + srow) * Dq + sseg * 8;
    const __nv_bfloat16* pAl = g_ctx_l + ((size_t)(b * Sq) + s0 + srow) * Dq + sseg * 8;
    const __nv_bfloat16* pBh = g_w_h + (size_t)srow * Dq + sseg * 8;
    const __nv_bfloat16* pBl = g_w_l + (size_t)srow * Dq + sseg * 8;

    // ldmatrix per-lane byte offsets
    const uint32_t aoff = (uint32_t)((wm * 64 + (lane & 15)) * RS + (lane >> 4) * 16);
    const uint32_t boff = (uint32_t)((wn * 32 + (lane & 15)) * RS + (lane >> 4) * 16);

    float acc[4][4][4];
#pragma unroll
    for (int mi = 0; mi < 4; mi++)
#pragma unroll
        for (int nj = 0; nj < 4; nj++)
#pragma unroll
            for (int r = 0; r < 4; r++) acc[mi][nj][r] = 0.f;
    float p[8];
#pragma unroll
    for (int i = 0; i < 8; i++) p[i] = 0.f;

    __syncthreads();   // pre_s/V_s ready

    // stage step g into buffer buf: A k-slab (g&15), B rows (g>>4)*128 + k-slab
    auto stage = [&](int g, int buf) {
        const int ka = (g & 15) * 32;                       // k elem offset
        const int hb = (g >> 4) * 128;                      // B row offset
        const uint32_t d = sdst + (uint32_t)(buf * TSZ);
        const __nv_bfloat16* a_h = pAh + ka;
        const __nv_bfloat16* a_l = pAl + ka;
        const __nv_bfloat16* b_h = pBh + (size_t)hb * Dq + ka;
        const __nv_bfloat16* b_l = pBl + (size_t)hb * Dq + ka;
        cp16(d + OF_AH,      a_h);
        cp16(d + OF_AH + 16, a_h + 8);
        cp16(d + OF_AL,      a_l);
        cp16(d + OF_AL + 16, a_l + 8);
        cp16(d + OF_BH,      b_h);
        cp16(d + OF_BH + 16, b_h + 8);
        cp16(d + OF_BL,      b_l);
        cp16(d + OF_BL + 16, b_l + 8);
    };

    stage(0, 0);
    cp_commit();

    for (int g = 0; g < 64; g++) {
        const int buf = g & 1;
        cp_wait0();
        __syncthreads();
        if (g < 63) { stage(g + 1, buf ^ 1); cp_commit(); }

        const uint32_t bo = sb + (uint32_t)(buf * TSZ);
#pragma unroll
        for (int kk = 0; kk < 2; kk++) {
            const uint32_t kb = kk * 32;
            uint32_t ah[4][4], al[4][4], bh[4][2], bl[4][2];
#pragma unroll
            for (int mi = 0; mi < 4; mi++) {
                ldsm_x4(ah[mi][0], ah[mi][1], ah[mi][2], ah[mi][3],
                        bo + OF_AH + aoff + mi * (16 * RS) + kb);
                ldsm_x4(al[mi][0], al[mi][1], al[mi][2], al[mi][3],
                        bo + OF_AL + aoff + mi * (16 * RS) + kb);
            }
#pragma unroll
            for (int ni = 0; ni < 2; ni++) {
                uint32_t r0, r1, r2, r3;
                ldsm_x4(r0, r1, r2, r3, bo + OF_BH + boff + ni * (16 * RS) + kb);
                bh[ni * 2][0] = r0;     bh[ni * 2][1] = r2;
                bh[ni * 2 + 1][0] = r1; bh[ni * 2 + 1][1] = r3;
                ldsm_x4(r0, r1, r2, r3, bo + OF_BL + boff + ni * (16 * RS) + kb);
                bl[ni * 2][0] = r0;     bl[ni * 2][1] = r2;
                bl[ni * 2 + 1][0] = r1; bl[ni * 2 + 1][1] = r3;
            }
            // product-outermost: 16 independent MMAs between acc reuses
#pragma unroll
            for (int mi = 0; mi < 4; mi++)
#pragma unroll
                for (int nj = 0; nj < 4; nj++)
                    mma16816(acc[mi][nj], ah[mi], bh[nj]);
#pragma unroll
            for (int mi = 0; mi < 4; mi++)
#pragma unroll
                for (int nj = 0; nj < 4; nj++)
                    mma16816(acc[mi][nj], ah[mi], bl[nj]);
#pragma unroll
            for (int mi = 0; mi < 4; mi++)
#pragma unroll
                for (int nj = 0; nj < 4; nj++)
                    mma16816(acc[mi][nj], al[mi], bh[nj]);
        }

        if ((g & 15) == 15) {
            // epilogue for h-chunk hc: p += V * tanh(pre + C); reset acc.
            const int hc = (g >> 4) * 128;
#pragma unroll
            for (int mi = 0; mi < 4; mi++)
#pragma unroll
                for (int nj = 0; nj < 4; nj++) {
                    const int n0 = hc + wn * 32 + nj * 8 + (lane & 3) * 2;
                    const float v0 = V_s[n0],     q0 = pre_s[n0];
                    const float v1 = V_s[n0 + 1], q1 = pre_s[n0 + 1];
                    p[mi * 2] += v0 * fast_tanh(q0 + acc[mi][nj][0])
                               + v1 * fast_tanh(q1 + acc[mi][nj][1]);
                    p[mi * 2 + 1] += v0 * fast_tanh(q0 + acc[mi][nj][2])
                                   + v1 * fast_tanh(q1 + acc[mi][nj][3]);
                    acc[mi][nj][0] = 0.f; acc[mi][nj][1] = 0.f;
                    acc[mi][nj][2] = 0.f; acc[mi][nj][3] = 0.f;
                }
        }
    }

    // reduce over lane quads, combine the 4 n-warps via smem
#pragma unroll
    for (int i = 0; i < 8; i++) {
        p[i] += __shfl_xor_sync(0xffffffffu, p[i], 1);
        p[i] += __shfl_xor_sync(0xffffffffu, p[i], 2);
    }
    if ((lane & 3) == 0) {
#pragma unroll
        for (int mi = 0; mi < 4; mi++)
#pragma unroll
            for (int hf = 0; hf < 2; hf++) {
                const int row = wm * 64 + mi * 16 + (lane >> 2) + hf * 8;
                attw[wn * 128 + row] = p[mi * 2 + hf];
            }
    }
    __syncthreads();
    if (tid < 128)
        g_att[b * Sq + s0 + tid] = (attw[tid] + attw[128 + tid])
                                 + (attw[256 + tid] + attw[384 + tid]);
}

// ---------------------------------------------------------------------------
// Masked softmax (mask int32).
// ---------------------------------------------------------------------------
__global__ void k_softmax(const int* __restrict__ mask,
                          float* __restrict__ alpha) {
    const int b = blockIdx.x, tid = threadIdx.x;
    __shared__ float red[8];
    float v[4];
#pragma unroll
    for (int i = 0; i < 4; i++) {
        const int s = tid + i * 256;
        const float a = g_att[b * Sq + s];
        v[i] = mask[b * Sq + s] ? -INFINITY : a;
    }
    float m = fmaxf(fmaxf(v[0], v[1]), fmaxf(v[2], v[3]));
#pragma unroll
    for (int o = 16; o; o >>= 1) m = fmaxf(m, __shfl_xor_sync(~0u, m, o));
    if ((tid & 31) == 0) red[tid >> 5] = m;
    __syncthreads();
    m = red[0];
#pragma unroll
    for (int i = 1; i < 8; i++) m = fmaxf(m, red[i]);
    __syncthreads();
    float e[4], sum = 0.f;
#pragma unroll
    for (int i = 0; i < 4; i++) { e[i] = expf(v[i] - m); sum += e[i]; }
#pragma unroll
    for (int o = 16; o; o >>= 1) sum += __shfl_xor_sync(~0u, sum, o);
    if ((tid & 31) == 0) red[tid >> 5] = sum;
    __syncthreads();
    sum = 0.f;
#pragma unroll
    for (int i = 0; i < 8; i++) sum += red[i];
    const float inv = 1.f / sum;
#pragma unroll
    for (int i = 0; i < 4; i++)
        alpha[b * Sq + tid + i * 256] = e[i] * inv;
}

// ---------------------------------------------------------------------------
// c_bar partials + reduce (deterministic).
// ---------------------------------------------------------------------------
__global__ void k_cbar(const float* __restrict__ context,
                       const float* __restrict__ alpha) {
    const int b  = blockIdx.z;
    const int sc = blockIdx.y;
    const int d  = blockIdx.x * 256 + threadIdx.x;
    const int s0 = sc * 256;
    __shared__ float al[256];
    al[threadIdx.x] = alpha[b * Sq + s0 + threadIdx.x];
    __syncthreads();
    const float* cp = context + ((size_t)b * Sq + s0) * Dq + d;
    float a0 = 0.f, a1 = 0.f, a2 = 0.f, a3 = 0.f;
    for (int s = 0; s < 256; s += 4) {
        a0 += al[s + 0] * cp[(size_t)(s + 0) * Dq];
        a1 += al[s + 1] * cp[(size_t)(s + 1) * Dq];
        a2 += al[s + 2] * cp[(size_t)(s + 2) * Dq];
        a3 += al[s + 3] * cp[(size_t)(s + 3) * Dq];
    }
    g_cbar_part[sc][b * Dq + d] = (a0 + a1) + (a2 + a3);
}
__global__ void k_cbar_reduce() {
    const int i = blockIdx.x * 256 + threadIdx.x;
    g_cbar[i] = (g_cbar_part[0][i] + g_cbar_part[1][i])
              + (g_cbar_part[2][i] + g_cbar_part[3][i]);
}

// ---------------------------------------------------------------------------
extern "C" void kernel_launch(void* const* d_in, const int* in_sizes, int n_in,
                              void* d_out, int out_size) {
    const float* input   = (const float*)d_in[0];
    const float* context = (const float*)d_in[1];
    const int*   mask    = (const int*)d_in[2];
    const float* W_in    = (const float*)d_in[3];
    const float* b_in    = (const float*)d_in[4];
    const float* W_ctx   = (const float*)d_in[5];
    const float* b_ctx   = (const float*)d_in[6];
    const float* V       = (const float*)d_in[7];

    float* hidden = (float*)d_out;
    float* alpha  = (float*)d_out + Bq * Hq;

    float *p_inp = nullptr, *p_cbar = nullptr;
    void  *p_ch = nullptr, *p_cl = nullptr, *p_wh = nullptr, *p_wl = nullptr;
    cudaGetSymbolAddress((void**)&p_inp,  g_inp);
    cudaGetSymbolAddress((void**)&p_cbar, g_cbar);
    cudaGetSymbolAddress(&p_ch, g_ctx_h);
    cudaGetSymbolAddress(&p_cl, g_ctx_l);
    cudaGetSymbolAddress(&p_wh, g_w_h);
    cudaGetSymbolAddress(&p_wl, g_w_l);

    cudaFuncSetAttribute(k_mma, cudaFuncAttributeMaxDynamicSharedMemorySize,
                         SMEM_SZ);

    const int n4c = Bq * Sq * Dq / 4;
    const int n4w = Hq * Dq / 4;
    k_split<<<n4c / 256, 256>>>((const float4*)context,
                                (uint2*)p_ch, (uint2*)p_cl, n4c);
    k_split<<<n4w / 256, 256>>>((const float4*)W_ctx,
                                (uint2*)p_wh, (uint2*)p_wl, n4w);
    k_lin  <<<Bq, 256>>>(input, W_in, b_in, p_inp);
    k_mma  <<<dim3(Sq / 128, Bq), 256, SMEM_SZ>>>(b_ctx, V);
    k_softmax<<<Bq, 256>>>(mask, alpha);
    k_cbar <<<dim3(2, 4, Bq), 256>>>(context, alpha);
    k_cbar_reduce<<<Bq * Dq / 256, 256>>>();
    k_lin  <<<Bq, 256>>>(p_cbar, W_ctx, b_ctx, hidden);
}